// round 6
// baseline (speedup 1.0000x reference)
#include <cuda_runtime.h>
#include <cuda_bf16.h>
#include <math.h>

#define N_NODES 10000
#define N_EDGES 50000
#define IN_F    1433
#define OUT_F   256

// ---------------- device scratch (no allocations allowed) ----------------
__device__ float g_normed[(size_t)N_NODES * IN_F];   // normalized aggregate
__device__ int   g_count[N_NODES];
__device__ int   g_start[N_NODES + 1];
__device__ int   g_cursor[N_NODES];
__device__ int   g_src[N_EDGES];
__device__ int   g_edges_is32;

// ---------------- 0) detect edges dtype (int64 vs int32 layout) ----------------
// If the buffer is really int32 pairs, interpreting as int64 merges
// (dst,src) into one word: value >= 2^32 whenever src != 0 -> flagged.
__global__ void k_detect(const void* edges) {
    const long long* e64 = (const long long*)edges;
    int bad = 0;
    for (int i = 0; i < 64; i++) {           // reads 1KB, safe for either layout
        long long d = e64[2 * i];
        long long s = e64[2 * i + 1];
        if (d < 0 || d > N_NODES || s < 0 || s > N_NODES) bad++;
    }
    g_edges_is32 = (bad > 0) ? 1 : 0;
}

__device__ __forceinline__ void load_edge(const void* edges, int e,
                                          long long& dst, long long& src) {
    if (g_edges_is32) {
        const int* p = (const int*)edges;
        dst = p[2 * e];
        src = p[2 * e + 1];
    } else {
        const long long* p = (const long long*)edges;
        dst = p[2 * e];
        src = p[2 * e + 1];
    }
}

// ---------------- 1) zero histogram ----------------
__global__ void k_zero() {
    int i = blockIdx.x * blockDim.x + threadIdx.x;
    if (i < N_NODES) g_count[i] = 0;
}

// ---------------- 2) histogram of valid edges by dst ----------------
__global__ void k_hist(const void* __restrict__ edges) {
    int e = blockIdx.x * blockDim.x + threadIdx.x;
    if (e < N_EDGES) {
        long long dst, src;
        load_edge(edges, e, dst, src);
        if (src >= 0 && src < N_NODES && dst >= 0 && dst < N_NODES)
            atomicAdd(&g_count[(int)dst], 1);
    }
}

// ---------------- 3) exclusive scan (single block) ----------------
__global__ void k_scan() {
    __shared__ int part[1024];
    const int CH = (N_NODES + 1023) / 1024;  // 10
    int t = threadIdx.x;
    int base = t * CH;
    int s = 0;
    for (int i = 0; i < CH; i++) {
        int idx = base + i;
        if (idx < N_NODES) s += g_count[idx];
    }
    part[t] = s;
    __syncthreads();
    // Hillis-Steele inclusive scan
    for (int off = 1; off < 1024; off <<= 1) {
        int v = (t >= off) ? part[t - off] : 0;
        __syncthreads();
        part[t] += v;
        __syncthreads();
    }
    int run = part[t] - s;  // exclusive prefix at this thread's base
    for (int i = 0; i < CH; i++) {
        int idx = base + i;
        if (idx < N_NODES) {
            g_start[idx]  = run;
            g_cursor[idx] = run;
            run += g_count[idx];
        }
    }
    if (t == 0) g_start[N_NODES] = part[1023];
}

// ---------------- 4) bucket edges by dst ----------------
__global__ void k_fill(const void* __restrict__ edges) {
    int e = blockIdx.x * blockDim.x + threadIdx.x;
    if (e < N_EDGES) {
        long long dst, src;
        load_edge(edges, e, dst, src);
        if (src >= 0 && src < N_NODES && dst >= 0 && dst < N_NODES) {
            int p = atomicAdd(&g_cursor[(int)dst], 1);
            if (p >= 0 && p < N_EDGES) g_src[p] = (int)src;
        }
    }
}

// ---------------- 5) atomic-free aggregate + noise + L2 normalize ----------------
// one block per destination row, 256 threads, 6 feature chunks per thread
__global__ void __launch_bounds__(256) k_agg(const float* __restrict__ x,
                                             const float* __restrict__ noise) {
    int row = blockIdx.x;
    int t = threadIdx.x;
    size_t rb = (size_t)row * IN_F;

    float acc[6];
#pragma unroll
    for (int j = 0; j < 6; j++) {
        int f = t + j * 256;
        acc[j] = (f < IN_F) ? noise[rb + f] : 0.0f;
    }

    int s = g_start[row], e = g_start[row + 1];
    for (int ei = s; ei < e; ei++) {
        const float* ip = x + (size_t)g_src[ei] * IN_F;
#pragma unroll
        for (int j = 0; j < 6; j++) {
            int f = t + j * 256;
            if (f < IN_F) acc[j] += ip[f];
        }
    }

    float ss = 0.0f;
#pragma unroll
    for (int j = 0; j < 6; j++) ss += acc[j] * acc[j];

    __shared__ float red[256];
    red[t] = ss;
    __syncthreads();
    for (int o = 128; o > 0; o >>= 1) {
        if (t < o) red[t] += red[t + o];
        __syncthreads();
    }
    float nrm = fmaxf(sqrtf(red[0]), 1e-12f);
    float rn = 1.0f / nrm;

#pragma unroll
    for (int j = 0; j < 6; j++) {
        int f = t + j * 256;
        if (f < IN_F) g_normed[rb + f] = acc[j] * rn;
    }
}

// ---------------- 6) fp32 tiled GEMM: out = normed @ W + bias ----------------
// BM=128, BN=64, BK=16, 256 threads, 8x4 micro-tile per thread
__global__ void __launch_bounds__(256) k_gemm(const float* __restrict__ W,
                                              const float* __restrict__ bias,
                                              float* __restrict__ out) {
    __shared__ float As[16][128];
    __shared__ float Bs[16][64];

    int tid = threadIdx.x;
    int tx = tid & 15;        // 0..15  -> 4 cols each
    int ty = tid >> 4;        // 0..15  -> 8 rows each
    int m0 = blockIdx.x * 128;
    int n0 = blockIdx.y * 64;

    // A loader: thread -> (row am, 8 consecutive k starting at ak8)
    int am  = tid >> 1;          // 0..127
    int ak8 = (tid & 1) * 8;     // 0 or 8
    // B loader: thread -> (k bk, 4 consecutive n)
    int bk  = tid >> 4;          // 0..15
    int bn4 = (tid & 15) * 4;    // 0..60

    float acc[8][4];
#pragma unroll
    for (int i = 0; i < 8; i++)
#pragma unroll
        for (int j = 0; j < 4; j++) acc[i][j] = 0.0f;

    for (int k0 = 0; k0 < IN_F; k0 += 16) {
        // load A tile (transposed into [k][m]); 8 elems per thread
        int row = m0 + am;
        const float* arow = g_normed + (size_t)row * IN_F;
#pragma unroll
        for (int i = 0; i < 8; i++) {
            int k = k0 + ak8 + i;
            As[ak8 + i][am] = (row < N_NODES && k < IN_F) ? arow[k] : 0.0f;
        }
        // load B tile: float4 per thread
        {
            int k = k0 + bk;
            float4 v = make_float4(0.f, 0.f, 0.f, 0.f);
            if (k < IN_F) v = *(const float4*)&W[(size_t)k * OUT_F + n0 + bn4];
            *(float4*)&Bs[bk][bn4] = v;
        }
        __syncthreads();

#pragma unroll
        for (int kk = 0; kk < 16; kk++) {
            float4 a0 = *(const float4*)&As[kk][ty * 8];
            float4 a1 = *(const float4*)&As[kk][ty * 8 + 4];
            float4 b  = *(const float4*)&Bs[kk][tx * 4];
            float av[8] = {a0.x, a0.y, a0.z, a0.w, a1.x, a1.y, a1.z, a1.w};
            float bv[4] = {b.x, b.y, b.z, b.w};
#pragma unroll
            for (int i = 0; i < 8; i++)
#pragma unroll
                for (int j = 0; j < 4; j++) acc[i][j] += av[i] * bv[j];
        }
        __syncthreads();
    }

    // epilogue: bias + store
    float bv[4];
#pragma unroll
    for (int j = 0; j < 4; j++) bv[j] = bias[n0 + tx * 4 + j];
#pragma unroll
    for (int i = 0; i < 8; i++) {
        int row = m0 + ty * 8 + i;
        if (row < N_NODES) {
            float4 o;
            o.x = acc[i][0] + bv[0];
            o.y = acc[i][1] + bv[1];
            o.z = acc[i][2] + bv[2];
            o.w = acc[i][3] + bv[3];
            *(float4*)&out[(size_t)row * OUT_F + n0 + tx * 4] = o;
        }
    }
}

// ---------------- launch ----------------
extern "C" void kernel_launch(void* const* d_in, const int* in_sizes, int n_in,
                              void* d_out, int out_size) {
    // Locate inputs by element count (robust to ordering surprises).
    const float* x     = nullptr;   // [10000,1433] -> 14330000
    const void*  edges = nullptr;   // [50000,2]    -> 100000
    const float* W     = nullptr;   // [1433,256]   -> 366848
    const float* bias  = nullptr;   // [256]        -> 256
    const float* noise = nullptr;   // [10000,1433] -> 14330000 (second occurrence)

    for (int i = 0; i < n_in; i++) {
        int sz = in_sizes[i];
        if (sz == N_EDGES * 2)            edges = d_in[i];
        else if (sz == IN_F * OUT_F)      W     = (const float*)d_in[i];
        else if (sz == OUT_F)             bias  = (const float*)d_in[i];
        else if (sz == N_NODES * IN_F) {
            if (!x) x = (const float*)d_in[i];
            else    noise = (const float*)d_in[i];
        }
    }
    float* out = (float*)d_out;
    (void)out_size;

    k_detect<<<1, 1>>>(edges);
    k_zero<<<(N_NODES + 255) / 256, 256>>>();
    k_hist<<<(N_EDGES + 255) / 256, 256>>>(edges);
    k_scan<<<1, 1024>>>();
    k_fill<<<(N_EDGES + 255) / 256, 256>>>(edges);
    k_agg<<<N_NODES, 256>>>(x, noise);

    dim3 gg((N_NODES + 127) / 128, OUT_F / 64);
    k_gemm<<<gg, 256>>>(W, bias, out);
}

// round 8
// speedup vs baseline: 1.9552x; 1.9552x over previous
#include <cuda_runtime.h>
#include <cuda_bf16.h>
#include <math.h>
#include <cstdint>

#define N_NODES 10000
#define N_EDGES 50000
#define IN_F    1433
#define OUT_F   256
#define K_PAD   1440              // 45 * 32
#define NCHUNK  45                // K chunks of 32

// ---------------- device scratch (no allocations allowed) ----------------
__device__ __nv_bfloat16 g_a_hi[(size_t)N_NODES * K_PAD];
__device__ __nv_bfloat16 g_a_lo[(size_t)N_NODES * K_PAD];
__device__ __nv_bfloat16 g_w_hi[(size_t)K_PAD * OUT_F];   // [k][n]
__device__ __nv_bfloat16 g_w_lo[(size_t)K_PAD * OUT_F];
__device__ int g_count[N_NODES];
__device__ int g_start[N_NODES + 1];
__device__ int g_cursor[N_NODES];
__device__ int g_src[N_EDGES];
__device__ int g_edges_is32;

// ---------------- helpers ----------------
__device__ __forceinline__ uint32_t smem_u32(const void* p) {
    uint32_t a;
    asm("{ .reg .u64 t; cvta.to.shared.u64 t, %1; cvt.u32.u64 %0, t; }" : "=r"(a) : "l"(p));
    return a;
}
__device__ __forceinline__ void cp16(uint32_t dst, const void* src, uint32_t bytes) {
    asm volatile("cp.async.cg.shared.global [%0], [%1], 16, %2;"
                 :: "r"(dst), "l"(src), "r"(bytes) : "memory");
}
__device__ __forceinline__ void cp_commit() {
    asm volatile("cp.async.commit_group;" ::: "memory");
}
template <int N>
__device__ __forceinline__ void cp_wait() {
    asm volatile("cp.async.wait_group %0;" :: "n"(N) : "memory");
}
__device__ __forceinline__ void ldsm_x4(uint32_t (&r)[4], uint32_t addr) {
    asm volatile("ldmatrix.sync.aligned.m8n8.x4.shared.b16 {%0,%1,%2,%3}, [%4];"
                 : "=r"(r[0]), "=r"(r[1]), "=r"(r[2]), "=r"(r[3]) : "r"(addr));
}
__device__ __forceinline__ void ldsm_x4_t(uint32_t (&r)[4], uint32_t addr) {
    asm volatile("ldmatrix.sync.aligned.m8n8.x4.trans.shared.b16 {%0,%1,%2,%3}, [%4];"
                 : "=r"(r[0]), "=r"(r[1]), "=r"(r[2]), "=r"(r[3]) : "r"(addr));
}
__device__ __forceinline__ void mma_bf16(float (&d)[4], const uint32_t (&a)[4],
                                         uint32_t b0, uint32_t b1) {
    asm volatile(
        "mma.sync.aligned.m16n8k16.row.col.f32.bf16.bf16.f32 "
        "{%0,%1,%2,%3}, {%4,%5,%6,%7}, {%8,%9}, {%0,%1,%2,%3};"
        : "+f"(d[0]), "+f"(d[1]), "+f"(d[2]), "+f"(d[3])
        : "r"(a[0]), "r"(a[1]), "r"(a[2]), "r"(a[3]), "r"(b0), "r"(b1));
}

// ---------------- 0+1) zero histogram + detect edges dtype ----------------
__global__ void k_zero_detect(const void* edges) {
    int i = blockIdx.x * blockDim.x + threadIdx.x;
    if (i < N_NODES) g_count[i] = 0;
    if (i == 0) {
        const long long* e64 = (const long long*)edges;
        int bad = 0;
        for (int j = 0; j < 64; j++) {
            long long d = e64[2 * j], s = e64[2 * j + 1];
            if (d < 0 || d > N_NODES || s < 0 || s > N_NODES) bad++;
        }
        g_edges_is32 = (bad > 0) ? 1 : 0;
    }
}

__device__ __forceinline__ void load_edge(const void* edges, int e,
                                          long long& dst, long long& src) {
    if (g_edges_is32) {
        const int* p = (const int*)edges;
        dst = p[2 * e]; src = p[2 * e + 1];
    } else {
        const long long* p = (const long long*)edges;
        dst = p[2 * e]; src = p[2 * e + 1];
    }
}

// ---------------- 2) histogram of valid edges by dst ----------------
__global__ void k_hist(const void* __restrict__ edges) {
    int e = blockIdx.x * blockDim.x + threadIdx.x;
    if (e < N_EDGES) {
        long long dst, src;
        load_edge(edges, e, dst, src);
        if (src >= 0 && src < N_NODES && dst >= 0 && dst < N_NODES)
            atomicAdd(&g_count[(int)dst], 1);
    }
}

// ---------------- 3) exclusive scan (single block, warp-shuffle) ----------------
__global__ void __launch_bounds__(1024) k_scan() {
    __shared__ int wsum[32];
    const int CH = 10;                       // 1024*10 >= 10000
    int t = threadIdx.x;
    int lane = t & 31, w = t >> 5;
    int base = t * CH;

    int s = 0;
    for (int i = 0; i < CH; i++) {
        int idx = base + i;
        if (idx < N_NODES) s += g_count[idx];
    }
    // warp inclusive scan
    int v = s;
#pragma unroll
    for (int off = 1; off < 32; off <<= 1) {
        int u = __shfl_up_sync(0xFFFFFFFFu, v, off);
        if (lane >= off) v += u;
    }
    if (lane == 31) wsum[w] = v;
    __syncthreads();
    if (w == 0) {
        int x = wsum[lane];
#pragma unroll
        for (int off = 1; off < 32; off <<= 1) {
            int u = __shfl_up_sync(0xFFFFFFFFu, x, off);
            if (lane >= off) x += u;
        }
        wsum[lane] = x;                      // inclusive warp totals
    }
    __syncthreads();
    int run = ((w > 0) ? wsum[w - 1] : 0) + (v - s);   // exclusive prefix
    for (int i = 0; i < CH; i++) {
        int idx = base + i;
        if (idx < N_NODES) {
            int c = g_count[idx];
            g_start[idx]  = run;
            g_cursor[idx] = run;
            run += c;
        }
    }
    if (t == 1023) g_start[N_NODES] = run;
}

// ---------------- 4) bucket edges by dst ----------------
__global__ void k_fill(const void* __restrict__ edges) {
    int e = blockIdx.x * blockDim.x + threadIdx.x;
    if (e < N_EDGES) {
        long long dst, src;
        load_edge(edges, e, dst, src);
        if (src >= 0 && src < N_NODES && dst >= 0 && dst < N_NODES) {
            int p = atomicAdd(&g_cursor[(int)dst], 1);
            if (p >= 0 && p < N_EDGES) g_src[p] = (int)src;
        }
    }
}

// ---------------- 5) aggregate + noise + L2 normalize -> bf16 hi/lo ----------------
__global__ void __launch_bounds__(256) k_agg(const float* __restrict__ x,
                                             const float* __restrict__ noise) {
    int row = blockIdx.x;
    int t = threadIdx.x;
    size_t rb = (size_t)row * IN_F;

    float acc[6];
#pragma unroll
    for (int j = 0; j < 6; j++) {
        int f = t + j * 256;
        acc[j] = (f < IN_F) ? noise[rb + f] : 0.0f;
    }

    int s = g_start[row], e = g_start[row + 1];
    for (int ei = s; ei < e; ei++) {
        const float* ip = x + (size_t)g_src[ei] * IN_F;
#pragma unroll
        for (int j = 0; j < 6; j++) {
            int f = t + j * 256;
            if (f < IN_F) acc[j] += ip[f];
        }
    }

    float ss = 0.0f;
#pragma unroll
    for (int j = 0; j < 6; j++) ss += acc[j] * acc[j];

    __shared__ float red[256];
    red[t] = ss;
    __syncthreads();
    for (int o = 128; o > 0; o >>= 1) {
        if (t < o) red[t] += red[t + o];
        __syncthreads();
    }
    float rn = 1.0f / fmaxf(sqrtf(red[0]), 1e-12f);

    size_t rb2 = (size_t)row * K_PAD;
#pragma unroll
    for (int j = 0; j < 6; j++) {
        int f = t + j * 256;
        if (f < K_PAD) {
            float v = (f < IN_F) ? acc[j] * rn : 0.0f;
            __nv_bfloat16 hi = __float2bfloat16(v);
            __nv_bfloat16 lo = __float2bfloat16(v - __bfloat162float(hi));
            g_a_hi[rb2 + f] = hi;
            g_a_lo[rb2 + f] = lo;
        }
    }
}

// ---------------- 5b) hi/lo split weight: [K,N] -> [K_PAD][N] ----------------
__global__ void __launch_bounds__(256) k_wprep(const float* __restrict__ W) {
    int n = threadIdx.x;                 // 0..255
    int k = blockIdx.x;                  // 0..K_PAD-1
    float v = (k < IN_F) ? W[(size_t)k * OUT_F + n] : 0.0f;
    __nv_bfloat16 hi = __float2bfloat16(v);
    __nv_bfloat16 lo = __float2bfloat16(v - __bfloat162float(hi));
    g_w_hi[(size_t)k * OUT_F + n] = hi;
    g_w_lo[(size_t)k * OUT_F + n] = lo;
}

// ---------------- 6) mma.sync bf16 split-precision GEMM ----------------
// CTA 128x64x32, 8 warps (4M x 2N), warp tile 32x32, cp.async 2-stage
#define A_STRIDE 80                     // bytes per A smem row (32 bf16 + 8 pad)
#define B_STRIDE 144                    // bytes per B smem row (64 bf16 + 8 pad)
#define A_TILE   (128 * A_STRIDE)       // 10240
#define B_TILE   (32 * B_STRIDE)        // 4608
#define ST_AHI   0
#define ST_ALO   A_TILE
#define ST_BHI   (2 * A_TILE)
#define ST_BLO   (2 * A_TILE + B_TILE)
#define STAGE_SZ (2 * A_TILE + 2 * B_TILE)   // 29696
#define GEMM_SMEM (2 * STAGE_SZ)             // 59392

__global__ void __launch_bounds__(256) k_gemm(const float* __restrict__ bias,
                                              float* __restrict__ out) {
    extern __shared__ char smem[];
    uint32_t sb = smem_u32(smem);
    int tid = threadIdx.x;
    int lane = tid & 31;
    int wid = tid >> 5;
    int wm = wid & 3;                   // 0..3 -> M offset wm*32
    int wn = wid >> 2;                  // 0..1 -> N offset wn*32
    int m0 = blockIdx.x * 128;
    int n0 = blockIdx.y * 64;

    float acc[2][4][4];
#pragma unroll
    for (int i = 0; i < 2; i++)
#pragma unroll
        for (int j = 0; j < 4; j++)
#pragma unroll
            for (int q = 0; q < 4; q++) acc[i][j][q] = 0.0f;

    // ---- async tile loader for chunk c into stage st ----
    auto issue = [&](int c, int st) {
        uint32_t sg = sb + st * STAGE_SZ;
        int k0 = c * 32;
        // A hi/lo: 512 uint4 each, 2 per thread
#pragma unroll
        for (int it = 0; it < 2; it++) {
            int idx = tid + it * 256;
            int r = idx >> 2, q = idx & 3;
            int row = m0 + r;
            uint32_t ok = (row < N_NODES) ? 16u : 0u;
            int rc = (row < N_NODES) ? row : (N_NODES - 1);
            size_t goff = (size_t)rc * K_PAD + k0 + q * 8;
            uint32_t doff = (uint32_t)(r * A_STRIDE + q * 16);
            cp16(sg + ST_AHI + doff, (const char*)g_a_hi + goff * 2, ok);
            cp16(sg + ST_ALO + doff, (const char*)g_a_lo + goff * 2, ok);
        }
        // B hi/lo: 256 uint4 each, 1 per thread
        {
            int r = tid >> 3, q = tid & 7;
            size_t goff = (size_t)(k0 + r) * OUT_F + n0 + q * 8;
            uint32_t doff = (uint32_t)(r * B_STRIDE + q * 16);
            cp16(sg + ST_BHI + doff, (const char*)g_w_hi + goff * 2, 16u);
            cp16(sg + ST_BLO + doff, (const char*)g_w_lo + goff * 2, 16u);
        }
        cp_commit();
    };

    issue(0, 0);

    for (int c = 0; c < NCHUNK; c++) {
        int st = c & 1;
        if (c + 1 < NCHUNK) {
            issue(c + 1, st ^ 1);
            cp_wait<1>();
        } else {
            cp_wait<0>();
        }
        __syncthreads();

        uint32_t sg = sb + st * STAGE_SZ;
#pragma unroll
        for (int kk = 0; kk < 2; kk++) {           // two k16 steps
            int kb = kk * 16;
            // A fragments (hi, lo) for 2 m-subtiles
            uint32_t ah[2][4], al[2][4];
#pragma unroll
            for (int mi = 0; mi < 2; mi++) {
                uint32_t ra = (uint32_t)((wm * 32 + mi * 16 + (lane & 15)) * A_STRIDE
                                         + kb * 2 + ((lane >> 4) << 4));
                ldsm_x4(ah[mi], sg + ST_AHI + ra);
                ldsm_x4(al[mi], sg + ST_ALO + ra);
            }
            // B fragments (hi, lo): two x4.trans loads cover n 0..31
            uint32_t bh[2][4], bl[2][4];
#pragma unroll
            for (int nh = 0; nh < 2; nh++) {
                uint32_t rb = (uint32_t)((kb + (lane & 15)) * B_STRIDE
                                         + (wn * 32 + nh * 16) * 2 + ((lane >> 4) << 4));
                ldsm_x4_t(bh[nh], sg + ST_BHI + rb);
                ldsm_x4_t(bl[nh], sg + ST_BLO + rb);
            }
            // 3 terms
#pragma unroll
            for (int mi = 0; mi < 2; mi++)
#pragma unroll
                for (int ni = 0; ni < 4; ni++) {
                    uint32_t b0h = bh[ni >> 1][(ni & 1) * 2];
                    uint32_t b1h = bh[ni >> 1][(ni & 1) * 2 + 1];
                    uint32_t b0l = bl[ni >> 1][(ni & 1) * 2];
                    uint32_t b1l = bl[ni >> 1][(ni & 1) * 2 + 1];
                    mma_bf16(acc[mi][ni], ah[mi], b0h, b1h);
                    mma_bf16(acc[mi][ni], al[mi], b0h, b1h);
                    mma_bf16(acc[mi][ni], ah[mi], b0l, b1l);
                }
        }
        __syncthreads();
    }

    // ---- epilogue: bias + store ----
#pragma unroll
    for (int mi = 0; mi < 2; mi++) {
        int r0 = m0 + wm * 32 + mi * 16 + (lane >> 2);
#pragma unroll
        for (int ni = 0; ni < 4; ni++) {
            int col = n0 + wn * 32 + ni * 8 + (lane & 3) * 2;
            float b0 = bias[col], b1 = bias[col + 1];
            if (r0 < N_NODES) {
                float2 v = make_float2(acc[mi][ni][0] + b0, acc[mi][ni][1] + b1);
                *(float2*)&out[(size_t)r0 * OUT_F + col] = v;
            }
            if (r0 + 8 < N_NODES) {
                float2 v = make_float2(acc[mi][ni][2] + b0, acc[mi][ni][3] + b1);
                *(float2*)&out[(size_t)(r0 + 8) * OUT_F + col] = v;
            }
        }
    }
}

// ---------------- launch ----------------
extern "C" void kernel_launch(void* const* d_in, const int* in_sizes, int n_in,
                              void* d_out, int out_size) {
    const float* x     = nullptr;
    const void*  edges = nullptr;
    const float* W     = nullptr;
    const float* bias  = nullptr;
    const float* noise = nullptr;

    for (int i = 0; i < n_in; i++) {
        int sz = in_sizes[i];
        if (sz == N_EDGES * 2)            edges = d_in[i];
        else if (sz == IN_F * OUT_F)      W     = (const float*)d_in[i];
        else if (sz == OUT_F)             bias  = (const float*)d_in[i];
        else if (sz == N_NODES * IN_F) {
            if (!x) x = (const float*)d_in[i];
            else    noise = (const float*)d_in[i];
        }
    }
    float* out = (float*)d_out;
    (void)out_size;

    cudaFuncSetAttribute(k_gemm, cudaFuncAttributeMaxDynamicSharedMemorySize, GEMM_SMEM);

    k_wprep<<<K_PAD, 256>>>(W);
    k_zero_detect<<<(N_NODES + 255) / 256, 256>>>(edges);
    k_hist<<<(N_EDGES + 255) / 256, 256>>>(edges);
    k_scan<<<1, 1024>>>();
    k_fill<<<(N_EDGES + 255) / 256, 256>>>(edges);
    k_agg<<<N_NODES, 256>>>(x, noise);

    dim3 gg((N_NODES + 127) / 128, OUT_F / 64);
    k_gemm<<<gg, 256, GEMM_SMEM>>>(bias, out);
}

// round 9
// speedup vs baseline: 2.1368x; 1.0929x over previous
#include <cuda_runtime.h>
#include <cuda_bf16.h>
#include <math.h>
#include <cstdint>

#define N_NODES 10000
#define N_EDGES 50000
#define IN_F    1433
#define OUT_F   256
#define K_PAD   1440              // 45 * 32
#define NCHUNK  45                // K chunks of 32

// ---------------- device scratch (no allocations allowed) ----------------
__device__ __nv_bfloat16 g_a_hi[(size_t)N_NODES * K_PAD];
__device__ __nv_bfloat16 g_a_lo[(size_t)N_NODES * K_PAD];
__device__ __nv_bfloat16 g_w_hi[(size_t)K_PAD * OUT_F];   // [k][n]
__device__ __nv_bfloat16 g_w_lo[(size_t)K_PAD * OUT_F];
__device__ int g_count[N_NODES];
__device__ int g_start[N_NODES + 1];   // after k_fill: bucket END per node
__device__ int g_src[N_EDGES];
__device__ int g_edges_is32;

// ---------------- helpers ----------------
__device__ __forceinline__ uint32_t smem_u32(const void* p) {
    uint32_t a;
    asm("{ .reg .u64 t; cvta.to.shared.u64 t, %1; cvt.u32.u64 %0, t; }" : "=r"(a) : "l"(p));
    return a;
}
__device__ __forceinline__ void cp16(uint32_t dst, const void* src, uint32_t bytes) {
    asm volatile("cp.async.cg.shared.global [%0], [%1], 16, %2;"
                 :: "r"(dst), "l"(src), "r"(bytes) : "memory");
}
__device__ __forceinline__ void cp_commit() {
    asm volatile("cp.async.commit_group;" ::: "memory");
}
template <int N>
__device__ __forceinline__ void cp_wait() {
    asm volatile("cp.async.wait_group %0;" :: "n"(N) : "memory");
}
__device__ __forceinline__ void ldsm_x4(uint32_t (&r)[4], uint32_t addr) {
    asm volatile("ldmatrix.sync.aligned.m8n8.x4.shared.b16 {%0,%1,%2,%3}, [%4];"
                 : "=r"(r[0]), "=r"(r[1]), "=r"(r[2]), "=r"(r[3]) : "r"(addr));
}
__device__ __forceinline__ void ldsm_x4_t(uint32_t (&r)[4], uint32_t addr) {
    asm volatile("ldmatrix.sync.aligned.m8n8.x4.trans.shared.b16 {%0,%1,%2,%3}, [%4];"
                 : "=r"(r[0]), "=r"(r[1]), "=r"(r[2]), "=r"(r[3]) : "r"(addr));
}
__device__ __forceinline__ void mma_bf16(float (&d)[4], const uint32_t (&a)[4],
                                         uint32_t b0, uint32_t b1) {
    asm volatile(
        "mma.sync.aligned.m16n8k16.row.col.f32.bf16.bf16.f32 "
        "{%0,%1,%2,%3}, {%4,%5,%6,%7}, {%8,%9}, {%0,%1,%2,%3};"
        : "+f"(d[0]), "+f"(d[1]), "+f"(d[2]), "+f"(d[3])
        : "r"(a[0]), "r"(a[1]), "r"(a[2]), "r"(a[3]), "r"(b0), "r"(b1));
}

// ---------------- 1) fused: W hi/lo split + zero hist + detect edge dtype ----------------
// blocks [0, K_PAD): wprep (k = blockIdx.x).  blocks [K_PAD, K_PAD+40): zero hist.
// block K_PAD warp 0: warp-parallel dtype detect (2 pairs per lane, ballot).
#define PREP_GRID (K_PAD + (N_NODES + 255) / 256)

__global__ void __launch_bounds__(256) k_prep(const float* __restrict__ W,
                                              const void* __restrict__ edges) {
    int b = blockIdx.x;
    if (b < K_PAD) {
        int n = threadIdx.x;
        int k = b;
        float v = (k < IN_F) ? W[(size_t)k * OUT_F + n] : 0.0f;
        __nv_bfloat16 hi = __float2bfloat16(v);
        __nv_bfloat16 lo = __float2bfloat16(v - __bfloat162float(hi));
        g_w_hi[(size_t)k * OUT_F + n] = hi;
        g_w_lo[(size_t)k * OUT_F + n] = lo;
    } else {
        int i = (b - K_PAD) * 256 + threadIdx.x;
        if (i < N_NODES) g_count[i] = 0;
        if (b == K_PAD && threadIdx.x < 32) {
            const long long* e64 = (const long long*)edges;
            int lane = threadIdx.x;
            int bad = 0;
#pragma unroll
            for (int j = 0; j < 2; j++) {
                int p = lane * 2 + j;
                long long d = e64[2 * p], s = e64[2 * p + 1];
                if (d < 0 || d > N_NODES || s < 0 || s > N_NODES) bad = 1;
            }
            unsigned m = __ballot_sync(0xFFFFFFFFu, bad);
            if (lane == 0) g_edges_is32 = (m != 0) ? 1 : 0;
        }
    }
}

__device__ __forceinline__ void load_edge(const void* edges, int e,
                                          long long& dst, long long& src) {
    if (g_edges_is32) {
        const int* p = (const int*)edges;
        dst = p[2 * e]; src = p[2 * e + 1];
    } else {
        const long long* p = (const long long*)edges;
        dst = p[2 * e]; src = p[2 * e + 1];
    }
}

// ---------------- 2) histogram of valid edges by dst ----------------
__global__ void k_hist(const void* __restrict__ edges) {
    int e = blockIdx.x * blockDim.x + threadIdx.x;
    if (e < N_EDGES) {
        long long dst, src;
        load_edge(edges, e, dst, src);
        if (src >= 0 && src < N_NODES && dst >= 0 && dst < N_NODES)
            atomicAdd(&g_count[(int)dst], 1);
    }
}

// ---------------- 3) exclusive scan (single block, warp-shuffle) ----------------
__global__ void __launch_bounds__(1024) k_scan() {
    __shared__ int wsum[32];
    const int CH = 10;
    int t = threadIdx.x;
    int lane = t & 31, w = t >> 5;
    int base = t * CH;

    int s = 0;
    int cnt[CH];
#pragma unroll
    for (int i = 0; i < CH; i++) {
        int idx = base + i;
        cnt[i] = (idx < N_NODES) ? g_count[idx] : 0;
        s += cnt[i];
    }
    int v = s;
#pragma unroll
    for (int off = 1; off < 32; off <<= 1) {
        int u = __shfl_up_sync(0xFFFFFFFFu, v, off);
        if (lane >= off) v += u;
    }
    if (lane == 31) wsum[w] = v;
    __syncthreads();
    if (w == 0) {
        int x = wsum[lane];
#pragma unroll
        for (int off = 1; off < 32; off <<= 1) {
            int u = __shfl_up_sync(0xFFFFFFFFu, x, off);
            if (lane >= off) x += u;
        }
        wsum[lane] = x;
    }
    __syncthreads();
    int run = ((w > 0) ? wsum[w - 1] : 0) + (v - s);
#pragma unroll
    for (int i = 0; i < CH; i++) {
        int idx = base + i;
        if (idx < N_NODES) {
            g_start[idx] = run;       // bucket start (k_fill turns it into end)
            run += cnt[i];
        }
    }
    if (t == 1023) g_start[N_NODES] = run;
}

// ---------------- 4) bucket edges by dst (mutates g_start -> bucket end) ----------------
__global__ void k_fill(const void* __restrict__ edges) {
    int e = blockIdx.x * blockDim.x + threadIdx.x;
    if (e < N_EDGES) {
        long long dst, src;
        load_edge(edges, e, dst, src);
        if (src >= 0 && src < N_NODES && dst >= 0 && dst < N_NODES) {
            int p = atomicAdd(&g_start[(int)dst], 1);
            if (p >= 0 && p < N_EDGES) g_src[p] = (int)src;
        }
    }
}

// ---------------- 5) aggregate + noise + L2 normalize -> bf16 hi/lo ----------------
__global__ void __launch_bounds__(256) k_agg(const float* __restrict__ x,
                                             const float* __restrict__ noise) {
    int row = blockIdx.x;
    int t = threadIdx.x;
    size_t rb = (size_t)row * IN_F;

    float acc[6];
#pragma unroll
    for (int j = 0; j < 6; j++) {
        int f = t + j * 256;
        acc[j] = (f < IN_F) ? noise[rb + f] : 0.0f;
    }

    int e = g_start[row];                  // bucket end (after k_fill)
    int s = e - g_count[row];              // bucket start
    int ei = s;
    for (; ei + 1 < e; ei += 2) {          // 2-edge unroll for MLP
        const float* ip0 = x + (size_t)g_src[ei] * IN_F;
        const float* ip1 = x + (size_t)g_src[ei + 1] * IN_F;
#pragma unroll
        for (int j = 0; j < 6; j++) {
            int f = t + j * 256;
            if (f < IN_F) acc[j] += ip0[f] + ip1[f];
        }
    }
    if (ei < e) {
        const float* ip = x + (size_t)g_src[ei] * IN_F;
#pragma unroll
        for (int j = 0; j < 6; j++) {
            int f = t + j * 256;
            if (f < IN_F) acc[j] += ip[f];
        }
    }

    float ss = 0.0f;
#pragma unroll
    for (int j = 0; j < 6; j++) ss += acc[j] * acc[j];

    __shared__ float red[256];
    red[t] = ss;
    __syncthreads();
    for (int o = 128; o > 0; o >>= 1) {
        if (t < o) red[t] += red[t + o];
        __syncthreads();
    }
    float rn = 1.0f / fmaxf(sqrtf(red[0]), 1e-12f);

    size_t rb2 = (size_t)row * K_PAD;
#pragma unroll
    for (int j = 0; j < 6; j++) {
        int f = t + j * 256;
        if (f < K_PAD) {
            float v = (f < IN_F) ? acc[j] * rn : 0.0f;
            __nv_bfloat16 hi = __float2bfloat16(v);
            __nv_bfloat16 lo = __float2bfloat16(v - __bfloat162float(hi));
            g_a_hi[rb2 + f] = hi;
            g_a_lo[rb2 + f] = lo;
        }
    }
}

// ---------------- 6) mma.sync bf16 split-precision GEMM ----------------
// CTA 96x64x32, 6 warps (1 warp = m16 x n64), cp.async 2-stage, 2 CTAs/SM
#define TILE_M   96
#define A_STRIDE 80                     // bytes per A smem row (32 bf16 + 8 pad)
#define B_STRIDE 144                    // bytes per B smem row (64 bf16 + 8 pad)
#define A_TILE   (TILE_M * A_STRIDE)    // 7680
#define B_TILE   (32 * B_STRIDE)        // 4608
#define ST_AHI   0
#define ST_ALO   A_TILE
#define ST_BHI   (2 * A_TILE)
#define ST_BLO   (2 * A_TILE + B_TILE)
#define STAGE_SZ (2 * A_TILE + 2 * B_TILE)   // 24576
#define GEMM_SMEM (2 * STAGE_SZ)             // 49152

__global__ void __launch_bounds__(192, 2) k_gemm(const float* __restrict__ bias,
                                                 float* __restrict__ out) {
    extern __shared__ char smem[];
    uint32_t sb = smem_u32(smem);
    int tid = threadIdx.x;
    int lane = tid & 31;
    int wm = tid >> 5;                  // 0..5 -> M offset wm*16
    int m0 = blockIdx.x * TILE_M;
    int n0 = blockIdx.y * 64;

    float acc[8][4];
#pragma unroll
    for (int j = 0; j < 8; j++)
#pragma unroll
        for (int q = 0; q < 4; q++) acc[j][q] = 0.0f;

    auto issue = [&](int c, int st) {
        uint32_t sg = sb + st * STAGE_SZ;
        int k0 = c * 32;
        // A hi/lo: 96 rows x 4 quads = 384 uint4, 2 per thread
#pragma unroll
        for (int it = 0; it < 2; it++) {
            int idx = tid + it * 192;
            int r = idx >> 2, q = idx & 3;
            int row = m0 + r;
            uint32_t ok = (row < N_NODES) ? 16u : 0u;
            int rc = (row < N_NODES) ? row : (N_NODES - 1);
            size_t goff = (size_t)rc * K_PAD + k0 + q * 8;
            uint32_t doff = (uint32_t)(r * A_STRIDE + q * 16);
            cp16(sg + ST_AHI + doff, (const char*)g_a_hi + goff * 2, ok);
            cp16(sg + ST_ALO + doff, (const char*)g_a_lo + goff * 2, ok);
        }
        // B hi/lo: 32 rows x 8 quads = 256 uint4, <=2 per thread
#pragma unroll
        for (int it = 0; it < 2; it++) {
            int idx = tid + it * 192;
            if (idx < 256) {
                int r = idx >> 3, q = idx & 7;
                size_t goff = (size_t)(k0 + r) * OUT_F + n0 + q * 8;
                uint32_t doff = (uint32_t)(r * B_STRIDE + q * 16);
                cp16(sg + ST_BHI + doff, (const char*)g_w_hi + goff * 2, 16u);
                cp16(sg + ST_BLO + doff, (const char*)g_w_lo + goff * 2, 16u);
            }
        }
        cp_commit();
    };

    issue(0, 0);

    for (int c = 0; c < NCHUNK; c++) {
        int st = c & 1;
        if (c + 1 < NCHUNK) {
            issue(c + 1, st ^ 1);
            cp_wait<1>();
        } else {
            cp_wait<0>();
        }
        __syncthreads();

        uint32_t sg = sb + st * STAGE_SZ;
#pragma unroll
        for (int kk = 0; kk < 2; kk++) {
            int kb = kk * 16;
            uint32_t ah[4], al[4];
            uint32_t ra = (uint32_t)((wm * 16 + (lane & 15)) * A_STRIDE
                                     + kb * 2 + ((lane >> 4) << 4));
            ldsm_x4(ah, sg + ST_AHI + ra);
            ldsm_x4(al, sg + ST_ALO + ra);

            uint32_t bh[4][4], bl[4][4];
#pragma unroll
            for (int nh = 0; nh < 4; nh++) {
                uint32_t rb = (uint32_t)((kb + (lane & 15)) * B_STRIDE
                                         + nh * 32 + ((lane >> 4) << 4));
                ldsm_x4_t(bh[nh], sg + ST_BHI + rb);
                ldsm_x4_t(bl[nh], sg + ST_BLO + rb);
            }
#pragma unroll
            for (int ni = 0; ni < 8; ni++) {
                uint32_t b0h = bh[ni >> 1][(ni & 1) * 2];
                uint32_t b1h = bh[ni >> 1][(ni & 1) * 2 + 1];
                uint32_t b0l = bl[ni >> 1][(ni & 1) * 2];
                uint32_t b1l = bl[ni >> 1][(ni & 1) * 2 + 1];
                mma_bf16(acc[ni], ah, b0h, b1h);
                mma_bf16(acc[ni], al, b0h, b1h);
                mma_bf16(acc[ni], ah, b0l, b1l);
            }
        }
        __syncthreads();
    }

    // ---- epilogue: bias + store ----
    int r0 = m0 + wm * 16 + (lane >> 2);
#pragma unroll
    for (int ni = 0; ni < 8; ni++) {
        int col = n0 + ni * 8 + (lane & 3) * 2;
        float b0 = bias[col], b1 = bias[col + 1];
        if (r0 < N_NODES) {
            float2 v = make_float2(acc[ni][0] + b0, acc[ni][1] + b1);
            *(float2*)&out[(size_t)r0 * OUT_F + col] = v;
        }
        if (r0 + 8 < N_NODES) {
            float2 v = make_float2(acc[ni][2] + b0, acc[ni][3] + b1);
            *(float2*)&out[(size_t)(r0 + 8) * OUT_F + col] = v;
        }
    }
}

// ---------------- launch ----------------
extern "C" void kernel_launch(void* const* d_in, const int* in_sizes, int n_in,
                              void* d_out, int out_size) {
    const float* x     = nullptr;
    const void*  edges = nullptr;
    const float* W     = nullptr;
    const float* bias  = nullptr;
    const float* noise = nullptr;

    for (int i = 0; i < n_in; i++) {
        int sz = in_sizes[i];
        if (sz == N_EDGES * 2)            edges = d_in[i];
        else if (sz == IN_F * OUT_F)      W     = (const float*)d_in[i];
        else if (sz == OUT_F)             bias  = (const float*)d_in[i];
        else if (sz == N_NODES * IN_F) {
            if (!x) x = (const float*)d_in[i];
            else    noise = (const float*)d_in[i];
        }
    }
    float* out = (float*)d_out;
    (void)out_size;

    cudaFuncSetAttribute(k_gemm, cudaFuncAttributeMaxDynamicSharedMemorySize, GEMM_SMEM);

    k_prep<<<PREP_GRID, 256>>>(W, edges);
    k_hist<<<(N_EDGES + 255) / 256, 256>>>(edges);
    k_scan<<<1, 1024>>>();
    k_fill<<<(N_EDGES + 255) / 256, 256>>>(edges);
    k_agg<<<N_NODES, 256>>>(x, noise);

    dim3 gg((N_NODES + TILE_M - 1) / TILE_M, OUT_F / 64);
    k_gemm<<<gg, 192, GEMM_SMEM>>>(bias, out);
}

// round 11
// speedup vs baseline: 2.2961x; 1.0746x over previous
#include <cuda_runtime.h>
#include <cuda_bf16.h>
#include <math.h>
#include <cstdint>

#define N_NODES 10000
#define N_EDGES 50000
#define IN_F    1433
#define OUT_F   256
#define K_PAD   1440              // 45 * 32
#define NCHUNK  45                // K chunks of 32

// ---------------- device scratch (no allocations allowed) ----------------
__device__ __nv_bfloat16 g_a_hi[(size_t)N_NODES * K_PAD];
__device__ __nv_bfloat16 g_a_lo[(size_t)N_NODES * K_PAD];
__device__ __nv_bfloat16 g_w_hi[(size_t)K_PAD * OUT_F];   // [k][n]
__device__ __nv_bfloat16 g_w_lo[(size_t)K_PAD * OUT_F];
__device__ int g_count[N_NODES];
__device__ int g_start[N_NODES + 1];   // after k_fill: bucket END per node
__device__ int g_src[N_EDGES];
__device__ int g_edges_is32;

// ---------------- helpers ----------------
__device__ __forceinline__ uint32_t smem_u32(const void* p) {
    uint32_t a;
    asm("{ .reg .u64 t; cvta.to.shared.u64 t, %1; cvt.u32.u64 %0, t; }" : "=r"(a) : "l"(p));
    return a;
}
__device__ __forceinline__ void cp16(uint32_t dst, const void* src, uint32_t bytes) {
    asm volatile("cp.async.cg.shared.global [%0], [%1], 16, %2;"
                 :: "r"(dst), "l"(src), "r"(bytes) : "memory");
}
__device__ __forceinline__ void cp_commit() {
    asm volatile("cp.async.commit_group;" ::: "memory");
}
template <int N>
__device__ __forceinline__ void cp_wait() {
    asm volatile("cp.async.wait_group %0;" :: "n"(N) : "memory");
}
__device__ __forceinline__ void ldsm_x4(uint32_t (&r)[4], uint32_t addr) {
    asm volatile("ldmatrix.sync.aligned.m8n8.x4.shared.b16 {%0,%1,%2,%3}, [%4];"
                 : "=r"(r[0]), "=r"(r[1]), "=r"(r[2]), "=r"(r[3]) : "r"(addr));
}
__device__ __forceinline__ void ldsm_x4_t(uint32_t (&r)[4], uint32_t addr) {
    asm volatile("ldmatrix.sync.aligned.m8n8.x4.trans.shared.b16 {%0,%1,%2,%3}, [%4];"
                 : "=r"(r[0]), "=r"(r[1]), "=r"(r[2]), "=r"(r[3]) : "r"(addr));
}
__device__ __forceinline__ void mma_bf16(float (&d)[4], const uint32_t (&a)[4],
                                         uint32_t b0, uint32_t b1) {
    asm volatile(
        "mma.sync.aligned.m16n8k16.row.col.f32.bf16.bf16.f32 "
        "{%0,%1,%2,%3}, {%4,%5,%6,%7}, {%8,%9}, {%0,%1,%2,%3};"
        : "+f"(d[0]), "+f"(d[1]), "+f"(d[2]), "+f"(d[3])
        : "r"(a[0]), "r"(a[1]), "r"(a[2]), "r"(a[3]), "r"(b0), "r"(b1));
}

// ---------------- 1) fused: W hi/lo split + zero hist + detect edge dtype ----------------
#define PREP_GRID (K_PAD + (N_NODES + 255) / 256)

__global__ void __launch_bounds__(256) k_prep(const float* __restrict__ W,
                                              const void* __restrict__ edges) {
    int b = blockIdx.x;
    if (b < K_PAD) {
        int n = threadIdx.x;
        int k = b;
        float v = (k < IN_F) ? W[(size_t)k * OUT_F + n] : 0.0f;
        __nv_bfloat16 hi = __float2bfloat16(v);
        __nv_bfloat16 lo = __float2bfloat16(v - __bfloat162float(hi));
        g_w_hi[(size_t)k * OUT_F + n] = hi;
        g_w_lo[(size_t)k * OUT_F + n] = lo;
    } else {
        int i = (b - K_PAD) * 256 + threadIdx.x;
        if (i < N_NODES) g_count[i] = 0;
        if (b == K_PAD && threadIdx.x < 32) {
            const long long* e64 = (const long long*)edges;
            int lane = threadIdx.x;
            int bad = 0;
#pragma unroll
            for (int j = 0; j < 2; j++) {
                int p = lane * 2 + j;
                long long d = e64[2 * p], s = e64[2 * p + 1];
                if (d < 0 || d > N_NODES || s < 0 || s > N_NODES) bad = 1;
            }
            unsigned m = __ballot_sync(0xFFFFFFFFu, bad);
            if (lane == 0) g_edges_is32 = (m != 0) ? 1 : 0;
        }
    }
}

__device__ __forceinline__ void load_edge(const void* edges, int e,
                                          long long& dst, long long& src) {
    if (g_edges_is32) {
        const int* p = (const int*)edges;
        dst = p[2 * e]; src = p[2 * e + 1];
    } else {
        const long long* p = (const long long*)edges;
        dst = p[2 * e]; src = p[2 * e + 1];
    }
}

// ---------------- 2) histogram of valid edges by dst ----------------
__global__ void k_hist(const void* __restrict__ edges) {
    int e = blockIdx.x * blockDim.x + threadIdx.x;
    if (e < N_EDGES) {
        long long dst, src;
        load_edge(edges, e, dst, src);
        if (src >= 0 && src < N_NODES && dst >= 0 && dst < N_NODES)
            atomicAdd(&g_count[(int)dst], 1);
    }
}

// ---------------- 3) exclusive scan (single block, warp-shuffle) ----------------
__global__ void __launch_bounds__(1024) k_scan() {
    __shared__ int wsum[32];
    const int CH = 10;
    int t = threadIdx.x;
    int lane = t & 31, w = t >> 5;
    int base = t * CH;

    int s = 0;
    int cnt[CH];
#pragma unroll
    for (int i = 0; i < CH; i++) {
        int idx = base + i;
        cnt[i] = (idx < N_NODES) ? g_count[idx] : 0;
        s += cnt[i];
    }
    int v = s;
#pragma unroll
    for (int off = 1; off < 32; off <<= 1) {
        int u = __shfl_up_sync(0xFFFFFFFFu, v, off);
        if (lane >= off) v += u;
    }
    if (lane == 31) wsum[w] = v;
    __syncthreads();
    if (w == 0) {
        int x = wsum[lane];
#pragma unroll
        for (int off = 1; off < 32; off <<= 1) {
            int u = __shfl_up_sync(0xFFFFFFFFu, x, off);
            if (lane >= off) x += u;
        }
        wsum[lane] = x;
    }
    __syncthreads();
    int run = ((w > 0) ? wsum[w - 1] : 0) + (v - s);
#pragma unroll
    for (int i = 0; i < CH; i++) {
        int idx = base + i;
        if (idx < N_NODES) {
            g_start[idx] = run;       // bucket start (k_fill turns it into end)
            run += cnt[i];
        }
    }
    if (t == 1023) g_start[N_NODES] = run;
}

// ---------------- 4) bucket edges by dst (mutates g_start -> bucket end) ----------------
__global__ void k_fill(const void* __restrict__ edges) {
    int e = blockIdx.x * blockDim.x + threadIdx.x;
    if (e < N_EDGES) {
        long long dst, src;
        load_edge(edges, e, dst, src);
        if (src >= 0 && src < N_NODES && dst >= 0 && dst < N_NODES) {
            int p = atomicAdd(&g_start[(int)dst], 1);
            if (p >= 0 && p < N_EDGES) g_src[p] = (int)src;
        }
    }
}

// ---------------- 5) aggregate + noise + L2 normalize -> bf16 hi/lo ----------------
__global__ void __launch_bounds__(256) k_agg(const float* __restrict__ x,
                                             const float* __restrict__ noise) {
    int row = blockIdx.x;
    int t = threadIdx.x;
    size_t rb = (size_t)row * IN_F;

    float acc[6];
#pragma unroll
    for (int j = 0; j < 6; j++) {
        int f = t + j * 256;
        acc[j] = (f < IN_F) ? noise[rb + f] : 0.0f;
    }

    int e = g_start[row];                  // bucket end (after k_fill)
    int s = e - g_count[row];              // bucket start
    int ei = s;
    for (; ei + 3 < e; ei += 4) {          // 4-edge unroll for MLP
        const float* ip0 = x + (size_t)g_src[ei] * IN_F;
        const float* ip1 = x + (size_t)g_src[ei + 1] * IN_F;
        const float* ip2 = x + (size_t)g_src[ei + 2] * IN_F;
        const float* ip3 = x + (size_t)g_src[ei + 3] * IN_F;
#pragma unroll
        for (int j = 0; j < 6; j++) {
            int f = t + j * 256;
            if (f < IN_F) acc[j] += (ip0[f] + ip1[f]) + (ip2[f] + ip3[f]);
        }
    }
    for (; ei < e; ei++) {
        const float* ip = x + (size_t)g_src[ei] * IN_F;
#pragma unroll
        for (int j = 0; j < 6; j++) {
            int f = t + j * 256;
            if (f < IN_F) acc[j] += ip[f];
        }
    }

    float ss = 0.0f;
#pragma unroll
    for (int j = 0; j < 6; j++) ss += acc[j] * acc[j];

    __shared__ float red[256];
    red[t] = ss;
    __syncthreads();
    for (int o = 128; o > 0; o >>= 1) {
        if (t < o) red[t] += red[t + o];
        __syncthreads();
    }
    float rn = 1.0f / fmaxf(sqrtf(red[0]), 1e-12f);

    size_t rb2 = (size_t)row * K_PAD;
#pragma unroll
    for (int j = 0; j < 6; j++) {
        int f = t + j * 256;
        if (f < K_PAD) {
            float v = (f < IN_F) ? acc[j] * rn : 0.0f;
            __nv_bfloat16 hi = __float2bfloat16(v);
            __nv_bfloat16 lo = __float2bfloat16(v - __bfloat162float(hi));
            g_a_hi[rb2 + f] = hi;
            g_a_lo[rb2 + f] = lo;
        }
    }
}

// ---------------- 6) mma.sync bf16 split-precision GEMM ----------------
// CTA 96x64x32, 6 warps (1 warp = m16 x n64), cp.async 2-stage, 3 CTAs/SM
#define TILE_M   96
#define A_STRIDE 80                     // bytes per A smem row (32 bf16 + 8 pad)
#define B_STRIDE 144                    // bytes per B smem row (64 bf16 + 8 pad)
#define A_TILE   (TILE_M * A_STRIDE)    // 7680
#define B_TILE   (32 * B_STRIDE)        // 4608
#define ST_AHI   0
#define ST_ALO   A_TILE
#define ST_BHI   (2 * A_TILE)
#define ST_BLO   (2 * A_TILE + B_TILE)
#define STAGE_SZ (2 * A_TILE + 2 * B_TILE)   // 24576
#define GEMM_SMEM (2 * STAGE_SZ)             // 49152

__global__ void __launch_bounds__(192, 3) k_gemm(const float* __restrict__ bias,
                                                 float* __restrict__ out) {
    extern __shared__ char smem[];
    uint32_t sb = smem_u32(smem);
    int tid = threadIdx.x;
    int lane = tid & 31;
    int wm = tid >> 5;                  // 0..5 -> M offset wm*16
    int m0 = blockIdx.x * TILE_M;
    int n0 = blockIdx.y * 64;

    float acc[8][4];
#pragma unroll
    for (int j = 0; j < 8; j++)
#pragma unroll
        for (int q = 0; q < 4; q++) acc[j][q] = 0.0f;

    auto issue = [&](int c, int st) {
        uint32_t sg = sb + st * STAGE_SZ;
        int k0 = c * 32;
        // A hi/lo: 96 rows x 4 quads = 384 uint4, 2 per thread
#pragma unroll
        for (int it = 0; it < 2; it++) {
            int idx = tid + it * 192;
            int r = idx >> 2, q = idx & 3;
            int row = m0 + r;
            uint32_t ok = (row < N_NODES) ? 16u : 0u;
            int rc = (row < N_NODES) ? row : (N_NODES - 1);
            size_t goff = (size_t)rc * K_PAD + k0 + q * 8;
            uint32_t doff = (uint32_t)(r * A_STRIDE + q * 16);
            cp16(sg + ST_AHI + doff, (const char*)g_a_hi + goff * 2, ok);
            cp16(sg + ST_ALO + doff, (const char*)g_a_lo + goff * 2, ok);
        }
        // B hi/lo: 32 rows x 8 quads = 256 uint4, <=2 per thread
#pragma unroll
        for (int it = 0; it < 2; it++) {
            int idx = tid + it * 192;
            if (idx < 256) {
                int r = idx >> 3, q = idx & 7;
                size_t goff = (size_t)(k0 + r) * OUT_F + n0 + q * 8;
                uint32_t doff = (uint32_t)(r * B_STRIDE + q * 16);
                cp16(sg + ST_BHI + doff, (const char*)g_w_hi + goff * 2, 16u);
                cp16(sg + ST_BLO + doff, (const char*)g_w_lo + goff * 2, 16u);
            }
        }
        cp_commit();
    };

    issue(0, 0);

    for (int c = 0; c < NCHUNK; c++) {
        int st = c & 1;
        if (c + 1 < NCHUNK) {
            issue(c + 1, st ^ 1);
            cp_wait<1>();
        } else {
            cp_wait<0>();
        }
        __syncthreads();

        uint32_t sg = sb + st * STAGE_SZ;
#pragma unroll
        for (int kk = 0; kk < 2; kk++) {
            int kb = kk * 16;
            uint32_t ah[4], al[4];
            uint32_t ra = (uint32_t)((wm * 16 + (lane & 15)) * A_STRIDE
                                     + kb * 2 + ((lane >> 4) << 4));
            ldsm_x4(ah, sg + ST_AHI + ra);
            ldsm_x4(al, sg + ST_ALO + ra);

            uint32_t bh[4][4], bl[4][4];
#pragma unroll
            for (int nh = 0; nh < 4; nh++) {
                uint32_t rb = (uint32_t)((kb + (lane & 15)) * B_STRIDE
                                         + nh * 32 + ((lane >> 4) << 4));
                ldsm_x4_t(bh[nh], sg + ST_BHI + rb);
                ldsm_x4_t(bl[nh], sg + ST_BLO + rb);
            }
#pragma unroll
            for (int ni = 0; ni < 8; ni++) {
                uint32_t b0h = bh[ni >> 1][(ni & 1) * 2];
                uint32_t b1h = bh[ni >> 1][(ni & 1) * 2 + 1];
                uint32_t b0l = bl[ni >> 1][(ni & 1) * 2];
                uint32_t b1l = bl[ni >> 1][(ni & 1) * 2 + 1];
                mma_bf16(acc[ni], ah, b0h, b1h);
                mma_bf16(acc[ni], al, b0h, b1h);
                mma_bf16(acc[ni], ah, b0l, b1l);
            }
        }
        __syncthreads();
    }

    // ---- epilogue: bias + store ----
    int r0 = m0 + wm * 16 + (lane >> 2);
#pragma unroll
    for (int ni = 0; ni < 8; ni++) {
        int col = n0 + ni * 8 + (lane & 3) * 2;
        float b0 = bias[col], b1 = bias[col + 1];
        if (r0 < N_NODES) {
            float2 v = make_float2(acc[ni][0] + b0, acc[ni][1] + b1);
            *(float2*)&out[(size_t)r0 * OUT_F + col] = v;
        }
        if (r0 + 8 < N_NODES) {
            float2 v = make_float2(acc[ni][2] + b0, acc[ni][3] + b1);
            *(float2*)&out[(size_t)(r0 + 8) * OUT_F + col] = v;
        }
    }
}

// ---------------- launch ----------------
extern "C" void kernel_launch(void* const* d_in, const int* in_sizes, int n_in,
                              void* d_out, int out_size) {
    const float* x     = nullptr;
    const void*  edges = nullptr;
    const float* W     = nullptr;
    const float* bias  = nullptr;
    const float* noise = nullptr;

    for (int i = 0; i < n_in; i++) {
        int sz = in_sizes[i];
        if (sz == N_EDGES * 2)            edges = d_in[i];
        else if (sz == IN_F * OUT_F)      W     = (const float*)d_in[i];
        else if (sz == OUT_F)             bias  = (const float*)d_in[i];
        else if (sz == N_NODES * IN_F) {
            if (!x) x = (const float*)d_in[i];
            else    noise = (const float*)d_in[i];
        }
    }
    float* out = (float*)d_out;
    (void)out_size;

    cudaFuncSetAttribute(k_gemm, cudaFuncAttributeMaxDynamicSharedMemorySize, GEMM_SMEM);

    k_prep<<<PREP_GRID, 256>>>(W, edges);
    k_hist<<<(N_EDGES + 255) / 256, 256>>>(edges);
    k_scan<<<1, 1024>>>();
    k_fill<<<(N_EDGES + 255) / 256, 256>>>(edges);
    k_agg<<<N_NODES, 256>>>(x, noise);

    dim3 gg((N_NODES + TILE_M - 1) / TILE_M, OUT_F / 64);
    k_gemm<<<gg, 192, GEMM_SMEM>>>(bias, out);
}

// round 12
// speedup vs baseline: 2.5767x; 1.1222x over previous
#include <cuda_runtime.h>
#include <cuda_bf16.h>
#include <math.h>
#include <cstdint>

#define N_NODES 10000
#define N_EDGES 50000
#define IN_F    1433
#define OUT_F   256
#define K_PAD   1440              // 45 * 32
#define NCHUNK  45                // K chunks of 32

// ---------------- device scratch (no allocations allowed) ----------------
__device__ __nv_bfloat16 g_a_hi[(size_t)N_NODES * K_PAD];
__device__ __nv_bfloat16 g_a_lo[(size_t)N_NODES * K_PAD];
__device__ __nv_bfloat16 g_w_hi[(size_t)K_PAD * OUT_F];   // [k][n]
__device__ __nv_bfloat16 g_w_lo[(size_t)K_PAD * OUT_F];
__device__ int g_count[N_NODES];
__device__ int g_start[N_NODES + 1];   // after k_fill: bucket END per node
__device__ int g_src[N_EDGES];
__device__ int g_edges_is32;
__device__ int g_ticket;               // zero-init; reset after each use

// ---------------- helpers ----------------
__device__ __forceinline__ uint32_t smem_u32(const void* p) {
    uint32_t a;
    asm("{ .reg .u64 t; cvta.to.shared.u64 t, %1; cvt.u32.u64 %0, t; }" : "=r"(a) : "l"(p));
    return a;
}
__device__ __forceinline__ void cp16(uint32_t dst, const void* src, uint32_t bytes) {
    asm volatile("cp.async.cg.shared.global [%0], [%1], 16, %2;"
                 :: "r"(dst), "l"(src), "r"(bytes) : "memory");
}
__device__ __forceinline__ void cp_commit() {
    asm volatile("cp.async.commit_group;" ::: "memory");
}
template <int N>
__device__ __forceinline__ void cp_wait() {
    asm volatile("cp.async.wait_group %0;" :: "n"(N) : "memory");
}
__device__ __forceinline__ void ldsm_x4(uint32_t (&r)[4], uint32_t addr) {
    asm volatile("ldmatrix.sync.aligned.m8n8.x4.shared.b16 {%0,%1,%2,%3}, [%4];"
                 : "=r"(r[0]), "=r"(r[1]), "=r"(r[2]), "=r"(r[3]) : "r"(addr));
}
__device__ __forceinline__ void ldsm_x4_t(uint32_t (&r)[4], uint32_t addr) {
    asm volatile("ldmatrix.sync.aligned.m8n8.x4.trans.shared.b16 {%0,%1,%2,%3}, [%4];"
                 : "=r"(r[0]), "=r"(r[1]), "=r"(r[2]), "=r"(r[3]) : "r"(addr));
}
__device__ __forceinline__ void mma_bf16(float (&d)[4], const uint32_t (&a)[4],
                                         uint32_t b0, uint32_t b1) {
    asm volatile(
        "mma.sync.aligned.m16n8k16.row.col.f32.bf16.bf16.f32 "
        "{%0,%1,%2,%3}, {%4,%5,%6,%7}, {%8,%9}, {%0,%1,%2,%3};"
        : "+f"(d[0]), "+f"(d[1]), "+f"(d[2]), "+f"(d[3])
        : "r"(a[0]), "r"(a[1]), "r"(a[2]), "r"(a[3]), "r"(b0), "r"(b1));
}

// swizzles (byte offsets, tile-base-relative)
__device__ __forceinline__ uint32_t sw128(uint32_t off) { return off ^ ((off >> 3) & 0x70); }
__device__ __forceinline__ uint32_t sw64(uint32_t off)  { return off ^ ((off >> 3) & 0x30); }

// ---------------- 1) init: zero histogram + detect edge dtype ----------------
__global__ void __launch_bounds__(256) k_init(const void* __restrict__ edges) {
    int i = blockIdx.x * blockDim.x + threadIdx.x;
    if (i < N_NODES) g_count[i] = 0;
    if (blockIdx.x == 0 && threadIdx.x < 32) {
        const long long* e64 = (const long long*)edges;
        int lane = threadIdx.x;
        int bad = 0;
#pragma unroll
        for (int j = 0; j < 2; j++) {
            int p = lane * 2 + j;
            long long d = e64[2 * p], s = e64[2 * p + 1];
            if (d < 0 || d > N_NODES || s < 0 || s > N_NODES) bad = 1;
        }
        unsigned m = __ballot_sync(0xFFFFFFFFu, bad);
        if (lane == 0) g_edges_is32 = (m != 0) ? 1 : 0;
    }
}

__device__ __forceinline__ void load_edge(const void* edges, int e,
                                          long long& dst, long long& src) {
    if (g_edges_is32) {
        const int* p = (const int*)edges;
        dst = p[2 * e]; src = p[2 * e + 1];
    } else {
        const long long* p = (const long long*)edges;
        dst = p[2 * e]; src = p[2 * e + 1];
    }
}

// ---------------- 2) histogram + fused scan (last block via ticket) ----------------
#define HIST_GRID ((N_EDGES + 1023) / 1024)

__global__ void __launch_bounds__(1024) k_hist_scan(const void* __restrict__ edges) {
    int e = blockIdx.x * 1024 + threadIdx.x;
    if (e < N_EDGES) {
        long long dst, src;
        load_edge(edges, e, dst, src);
        if (src >= 0 && src < N_NODES && dst >= 0 && dst < N_NODES)
            atomicAdd(&g_count[(int)dst], 1);
    }

    __shared__ int lastFlag;
    __syncthreads();
    if (threadIdx.x == 0) {
        __threadfence();
        lastFlag = (atomicAdd(&g_ticket, 1) == (int)gridDim.x - 1);
    }
    __syncthreads();
    if (!lastFlag) return;
    __threadfence();

    // ---- exclusive scan over g_count (1024 threads, 10 bins each) ----
    __shared__ int wsum[32];
    const int CH = 10;
    int t = threadIdx.x;
    int lane = t & 31, w = t >> 5;
    int base = t * CH;

    int s = 0;
    int cnt[CH];
#pragma unroll
    for (int i = 0; i < CH; i++) {
        int idx = base + i;
        cnt[i] = (idx < N_NODES) ? g_count[idx] : 0;
        s += cnt[i];
    }
    int v = s;
#pragma unroll
    for (int off = 1; off < 32; off <<= 1) {
        int u = __shfl_up_sync(0xFFFFFFFFu, v, off);
        if (lane >= off) v += u;
    }
    if (lane == 31) wsum[w] = v;
    __syncthreads();
    if (w == 0) {
        int x = wsum[lane];
#pragma unroll
        for (int off = 1; off < 32; off <<= 1) {
            int u = __shfl_up_sync(0xFFFFFFFFu, x, off);
            if (lane >= off) x += u;
        }
        wsum[lane] = x;
    }
    __syncthreads();
    int run = ((w > 0) ? wsum[w - 1] : 0) + (v - s);
#pragma unroll
    for (int i = 0; i < CH; i++) {
        int idx = base + i;
        if (idx < N_NODES) {
            g_start[idx] = run;       // bucket start (k_fill turns it into end)
            run += cnt[i];
        }
    }
    if (t == 1023) g_start[N_NODES] = run;
    if (t == 0) g_ticket = 0;         // reset for next graph replay
}

// ---------------- 3) bucket edges by dst (mutates g_start -> bucket end) ----------------
__global__ void k_fill(const void* __restrict__ edges) {
    int e = blockIdx.x * blockDim.x + threadIdx.x;
    if (e < N_EDGES) {
        long long dst, src;
        load_edge(edges, e, dst, src);
        if (src >= 0 && src < N_NODES && dst >= 0 && dst < N_NODES) {
            int p = atomicAdd(&g_start[(int)dst], 1);
            if (p >= 0 && p < N_EDGES) g_src[p] = (int)src;
        }
    }
}

// ---------------- 4) aggregate + normalize -> bf16 hi/lo, PLUS W hi/lo split ----------------
// blocks [0, N_NODES): aggregate.  blocks [N_NODES, N_NODES+K_PAD): W split row k.
__global__ void __launch_bounds__(256) k_agg(const float* __restrict__ x,
                                             const float* __restrict__ noise,
                                             const float* __restrict__ W) {
    int b = blockIdx.x;
    if (b >= N_NODES) {                    // ---- W prep branch ----
        int k = b - N_NODES;
        int n = threadIdx.x;
        float v = (k < IN_F) ? W[(size_t)k * OUT_F + n] : 0.0f;
        __nv_bfloat16 hi = __float2bfloat16(v);
        __nv_bfloat16 lo = __float2bfloat16(v - __bfloat162float(hi));
        g_w_hi[(size_t)k * OUT_F + n] = hi;
        g_w_lo[(size_t)k * OUT_F + n] = lo;
        return;
    }

    int row = b;
    int t = threadIdx.x;
    size_t rb = (size_t)row * IN_F;

    float acc[6];
#pragma unroll
    for (int j = 0; j < 6; j++) {
        int f = t + j * 256;
        acc[j] = (f < IN_F) ? noise[rb + f] : 0.0f;
    }

    int e = g_start[row];                  // bucket end (after k_fill)
    int s = e - g_count[row];              // bucket start
    int ei = s;
    for (; ei + 3 < e; ei += 4) {          // 4-edge unroll for MLP
        const float* ip0 = x + (size_t)g_src[ei] * IN_F;
        const float* ip1 = x + (size_t)g_src[ei + 1] * IN_F;
        const float* ip2 = x + (size_t)g_src[ei + 2] * IN_F;
        const float* ip3 = x + (size_t)g_src[ei + 3] * IN_F;
#pragma unroll
        for (int j = 0; j < 6; j++) {
            int f = t + j * 256;
            if (f < IN_F) acc[j] += (ip0[f] + ip1[f]) + (ip2[f] + ip3[f]);
        }
    }
    for (; ei < e; ei++) {
        const float* ip = x + (size_t)g_src[ei] * IN_F;
#pragma unroll
        for (int j = 0; j < 6; j++) {
            int f = t + j * 256;
            if (f < IN_F) acc[j] += ip[f];
        }
    }

    float ss = 0.0f;
#pragma unroll
    for (int j = 0; j < 6; j++) ss += acc[j] * acc[j];

    __shared__ float red[256];
    red[t] = ss;
    __syncthreads();
    for (int o = 128; o > 0; o >>= 1) {
        if (t < o) red[t] += red[t + o];
        __syncthreads();
    }
    float rn = 1.0f / fmaxf(sqrtf(red[0]), 1e-12f);

    size_t rb2 = (size_t)row * K_PAD;
#pragma unroll
    for (int j = 0; j < 6; j++) {
        int f = t + j * 256;
        if (f < K_PAD) {
            float v = (f < IN_F) ? acc[j] * rn : 0.0f;
            __nv_bfloat16 hi = __float2bfloat16(v);
            __nv_bfloat16 lo = __float2bfloat16(v - __bfloat162float(hi));
            g_a_hi[rb2 + f] = hi;
            g_a_lo[rb2 + f] = lo;
        }
    }
}

// ---------------- 5) mma.sync bf16 split-precision GEMM ----------------
// CTA 96x64x32, 6 warps (warp = m16 x n64), XOR-swizzled smem, 3-stage cp.async
#define TILE_M   96
#define A_TILE   (TILE_M * 64)          // 6144 (rows of 64B, SW64)
#define B_TILE   (32 * 128)             // 4096 (rows of 128B, SW128)
#define ST_AHI   0
#define ST_ALO   A_TILE
#define ST_BHI   (2 * A_TILE)
#define ST_BLO   (2 * A_TILE + B_TILE)
#define STAGE_SZ (2 * A_TILE + 2 * B_TILE)   // 20480
#define NSTAGE   3
#define GEMM_SMEM (NSTAGE * STAGE_SZ)        // 61440

__global__ void __launch_bounds__(192, 3) k_gemm(const float* __restrict__ bias,
                                                 float* __restrict__ out) {
    extern __shared__ char smem[];
    uint32_t sb = smem_u32(smem);
    int tid = threadIdx.x;
    int lane = tid & 31;
    int wm = tid >> 5;                  // 0..5 -> M offset wm*16
    int m0 = blockIdx.x * TILE_M;
    int n0 = blockIdx.y * 64;

    float acc[8][4];
#pragma unroll
    for (int j = 0; j < 8; j++)
#pragma unroll
        for (int q = 0; q < 4; q++) acc[j][q] = 0.0f;

    auto issue = [&](int c, int st) {
        uint32_t sg = sb + st * STAGE_SZ;
        int k0 = c * 32;
        // A hi/lo: 96 rows x 64B = 384 uint4, 2 per thread (SW64)
#pragma unroll
        for (int it = 0; it < 2; it++) {
            int idx = tid + it * 192;
            int r = idx >> 2, q = idx & 3;
            int row = m0 + r;
            uint32_t ok = (row < N_NODES) ? 16u : 0u;
            int rc = (row < N_NODES) ? row : (N_NODES - 1);
            size_t goff = (size_t)rc * K_PAD + k0 + q * 8;
            uint32_t sw = sw64((uint32_t)(r * 64 + q * 16));
            cp16(sg + ST_AHI + sw, (const char*)g_a_hi + goff * 2, ok);
            cp16(sg + ST_ALO + sw, (const char*)g_a_lo + goff * 2, ok);
        }
        // B hi/lo: 32 rows x 128B = 256 uint4, <=2 per thread (SW128)
#pragma unroll
        for (int it = 0; it < 2; it++) {
            int idx = tid + it * 192;
            if (idx < 256) {
                int r = idx >> 3, q = idx & 7;
                size_t goff = (size_t)(k0 + r) * OUT_F + n0 + q * 8;
                uint32_t sw = sw128((uint32_t)(r * 128 + q * 16));
                cp16(sg + ST_BHI + sw, (const char*)g_w_hi + goff * 2, 16u);
                cp16(sg + ST_BLO + sw, (const char*)g_w_lo + goff * 2, 16u);
            }
        }
        cp_commit();
    };

    issue(0, 0);
    issue(1, 1);

    for (int c = 0; c < NCHUNK; c++) {
        int st = c % NSTAGE;
        if (c + 2 < NCHUNK) { issue(c + 2, (c + 2) % NSTAGE); cp_wait<2>(); }
        else if (c + 1 < NCHUNK) cp_wait<1>();
        else cp_wait<0>();
        __syncthreads();

        uint32_t sg = sb + st * STAGE_SZ;
#pragma unroll
        for (int kk = 0; kk < 2; kk++) {
            int kb = kk * 16;
            uint32_t ah[4], al[4];
            {
                int r = wm * 16 + (lane & 15);
                uint32_t off = (uint32_t)(r * 64 + kb * 2 + ((lane >> 4) << 4));
                uint32_t ra = sw64(off);
                ldsm_x4(ah, sg + ST_AHI + ra);
                ldsm_x4(al, sg + ST_ALO + ra);
            }
            uint32_t bh[4][4], bl[4][4];
#pragma unroll
            for (int nh = 0; nh < 4; nh++) {
                int r = kb + (lane & 15);
                uint32_t off = (uint32_t)(r * 128 + nh * 32 + ((lane >> 4) << 4));
                uint32_t rbb = sw128(off);
                ldsm_x4_t(bh[nh], sg + ST_BHI + rbb);
                ldsm_x4_t(bl[nh], sg + ST_BLO + rbb);
            }
#pragma unroll
            for (int ni = 0; ni < 8; ni++) {
                uint32_t b0h = bh[ni >> 1][(ni & 1) * 2];
                uint32_t b1h = bh[ni >> 1][(ni & 1) * 2 + 1];
                uint32_t b0l = bl[ni >> 1][(ni & 1) * 2];
                uint32_t b1l = bl[ni >> 1][(ni & 1) * 2 + 1];
                mma_bf16(acc[ni], ah, b0h, b1h);
                mma_bf16(acc[ni], al, b0h, b1h);
                mma_bf16(acc[ni], ah, b0l, b1l);
            }
        }
        __syncthreads();
    }

    // ---- epilogue: bias + store ----
    int r0 = m0 + wm * 16 + (lane >> 2);
#pragma unroll
    for (int ni = 0; ni < 8; ni++) {
        int col = n0 + ni * 8 + (lane & 3) * 2;
        float b0 = bias[col], b1 = bias[col + 1];
        if (r0 < N_NODES) {
            float2 v = make_float2(acc[ni][0] + b0, acc[ni][1] + b1);
            *(float2*)&out[(size_t)r0 * OUT_F + col] = v;
        }
        if (r0 + 8 < N_NODES) {
            float2 v = make_float2(acc[ni][2] + b0, acc[ni][3] + b1);
            *(float2*)&out[(size_t)(r0 + 8) * OUT_F + col] = v;
        }
    }
}

// ---------------- launch ----------------
extern "C" void kernel_launch(void* const* d_in, const int* in_sizes, int n_in,
                              void* d_out, int out_size) {
    const float* x     = nullptr;
    const void*  edges = nullptr;
    const float* W     = nullptr;
    const float* bias  = nullptr;
    const float* noise = nullptr;

    for (int i = 0; i < n_in; i++) {
        int sz = in_sizes[i];
        if (sz == N_EDGES * 2)            edges = d_in[i];
        else if (sz == IN_F * OUT_F)      W     = (const float*)d_in[i];
        else if (sz == OUT_F)             bias  = (const float*)d_in[i];
        else if (sz == N_NODES * IN_F) {
            if (!x) x = (const float*)d_in[i];
            else    noise = (const float*)d_in[i];
        }
    }
    float* out = (float*)d_out;
    (void)out_size;

    cudaFuncSetAttribute(k_gemm, cudaFuncAttributeMaxDynamicSharedMemorySize, GEMM_SMEM);

    k_init<<<(N_NODES + 255) / 256, 256>>>(edges);
    k_hist_scan<<<HIST_GRID, 1024>>>(edges);
    k_fill<<<(N_EDGES + 255) / 256, 256>>>(edges);
    k_agg<<<N_NODES + K_PAD, 256>>>(x, noise, W);

    dim3 gg((N_NODES + TILE_M - 1) / TILE_M, OUT_F / 64);
    k_gemm<<<gg, 192, GEMM_SMEM>>>(bias, out);
}